// round 3
// baseline (speedup 1.0000x reference)
#include <cuda_runtime.h>
#include <math.h>

#define BSZ 8
#define HN  512
#define LN  2048
#define D2N 32
#define CN  64          // chunk length
#define NC  (LN/CN)     // 32 chunks

// ---------------- scratch (device globals; no allocation allowed) ----------------
__device__ __align__(16) float  g_f [HN*LN];          // SSM kernel f[h][l]
__device__ __align__(16) float  g_k0[HN*LN];          // init-state kernel k0[h][l]
__device__ float2               g_V [HN*CN*D2N];      // [h][m][d] = w^{C-1-m}
__device__ __align__(16) float  g_P [HN*2*D2N*CN];    // [h][dd][j]; dd<32: Re(2Tq w^{j+1}), dd>=32: -Im(...)
__device__ float2               g_WC[HN*D2N];         // w^C
__device__ __align__(16) float  g_S [BSZ*HN*NC*2*D2N];// chunk states (A then in-place S)
__device__ __align__(16) float  g_g [BSZ*HN*LN];      // gelu(y)

// ---------------- K1: tables ----------------
__global__ void k_tables(const float* __restrict__ a, const float* __restrict__ th,
                         const float* __restrict__ bb, const float* __restrict__ cc,
                         const float* __restrict__ x0)
{
    int h = blockIdx.x;
    __shared__ float s_aa[D2N], s_th[D2N], s_q[D2N], s_cx[D2N];
    int tid = threadIdx.x;
    if (tid < D2N) {
        float av = a[h*D2N + tid];
        s_aa[tid] = -fabsf(av);
        s_th[tid] = th[h*D2N + tid];
        s_q [tid] = bb[h*D2N + tid] * cc[h*D2N + tid];
        s_cx[tid] = cc[h*D2N + tid] * x0[h*D2N + tid];
    }
    __syncthreads();
    const float T = 1.0f / (float)(LN - 1);

    // f and k0 (accurate math for safety)
    for (int l = tid; l < LN; l += blockDim.x) {
        float z = T * (float)l;
        float accf = 0.f, acck = 0.f;
        #pragma unroll 8
        for (int d = 0; d < D2N; d++) {
            float base = expf(s_aa[d]*z) * cosf(s_th[d]*z);
            accf += s_q[d]  * base;
            acck += s_cx[d] * base;
        }
        g_f [h*LN + l] = 2.0f*T*accf;
        g_k0[h*LN + l] = 2.0f*acck;
    }

    // per-(h,d) power tables
    if (tid < D2N) {
        int d = tid;
        float aa = s_aa[d], thd = s_th[d], q = s_q[d];
        for (int m = 0; m < CN; m++) {
            float k = (float)(CN - 1 - m);
            float e = expf(aa*T*k);
            g_V[(h*CN + m)*D2N + d] = make_float2(e*cosf(thd*T*k), e*sinf(thd*T*k));
        }
        {
            float k = (float)CN;
            float e = expf(aa*T*k);
            g_WC[h*D2N + d] = make_float2(e*cosf(thd*T*k), e*sinf(thd*T*k));
        }
        for (int j = 0; j < CN; j++) {
            float k = (float)(j + 1);
            float e = expf(aa*T*k);
            float pr =  2.0f*T*q*e*cosf(thd*T*k);
            float pi = -2.0f*T*q*e*sinf(thd*T*k);
            g_P[(h*2*D2N + d      )*CN + j] = pr;
            g_P[(h*2*D2N + D2N + d)*CN + j] = pi;
        }
    }
}

// ---------------- K2: per-chunk partial states A ----------------
__global__ void k_chunkA(const float* __restrict__ u)
{
    int row = blockIdx.x;          // b*HN + h
    int h = row & (HN-1);
    __shared__ float  u_s[LN];
    __shared__ float2 V_s[CN*D2N];
    int tid = threadIdx.x;         // 256
    for (int i = tid; i < LN; i += 256) u_s[i] = u[row*LN + i];
    const float2* Vg = g_V + h*CN*D2N;
    for (int i = tid; i < CN*D2N; i += 256) V_s[i] = Vg[i];
    __syncthreads();

    int d  = tid & 31;
    int c0 = tid >> 5;             // 0..7
    #pragma unroll
    for (int k = 0; k < 4; k++) {
        int c = c0 + 8*k;
        float ar = 0.f, ai = 0.f;
        const float* uc = u_s + c*CN;
        #pragma unroll 8
        for (int m = 0; m < CN; m++) {
            float2 v = V_s[m*D2N + d];
            float um = uc[m];
            ar += v.x * um;
            ai += v.y * um;
        }
        int idx = (row*NC + c)*2*D2N;
        g_S[idx + d]       = ar;
        g_S[idx + D2N + d] = ai;
    }
}

// ---------------- K3: cross-chunk state scan (in place) ----------------
__global__ void k_scan()
{
    int row = blockIdx.x*8 + (threadIdx.x >> 5);
    int d   = threadIdx.x & 31;
    float2 wc = g_WC[(row & (HN-1))*D2N + d];
    float sr = 0.f, si = 0.f;
    for (int c = 0; c < NC; c++) {
        int idx = (row*NC + c)*2*D2N;
        float ar = g_S[idx + d];
        float ai = g_S[idx + D2N + d];
        g_S[idx + d]       = sr;   // state entering chunk c
        g_S[idx + D2N + d] = si;
        float nsr = wc.x*sr - wc.y*si + ar;
        si        = wc.x*si + wc.y*sr + ai;
        sr = nsr;
    }
}

// ---------------- K4: intra-chunk conv + cross term + epilogue + GELU ----------------
__global__ void k_main(const float* __restrict__ u, const float* __restrict__ Din)
{
    int row = blockIdx.x;
    int h = row & (HN-1);
    __shared__ float u_s[LN];
    __shared__ float f_s[CN];
    __shared__ float P_s[2*D2N*CN];
    __shared__ float S_s[4*2*D2N];
    int tid = threadIdx.x;         // 256
    for (int i = tid; i < LN; i += 256) u_s[i] = u[row*LN + i];
    const float* Pg = g_P + h*2*D2N*CN;
    for (int i = tid; i < 2*D2N*CN; i += 256) P_s[i] = Pg[i];
    if (tid < CN) f_s[tid] = g_f[h*LN + tid];
    __syncthreads();

    float u0    = u_s[0];
    float coefU = Din[h] - 0.5f * f_s[0];
    int jj = tid & 63;
    int cl = tid >> 6;             // 0..3
    for (int g4 = 0; g4 < NC/4; g4++) {
        __syncthreads();
        S_s[tid] = g_S[row*NC*2*D2N + g4*256 + tid];   // 4 chunks' state vectors
        __syncthreads();
        int c = 4*g4 + cl;
        int l = c*CN + jj;
        float y = 0.f;
        const float* uc = u_s + c*CN;
        for (int m = 0; m <= jj; m++) y += uc[m] * f_s[jj - m];
        const float* Sv = S_s + cl*2*D2N;
        #pragma unroll 8
        for (int dd = 0; dd < 2*D2N; dd++) y += P_s[dd*CN + jj] * Sv[dd];
        y += g_k0[h*LN + l] + coefU*u_s[l] - 0.5f*g_f[h*LN + l]*u0;
        float ge = 0.5f * y * (1.0f + erff(y * 0.70710678118654752f));
        g_g[row*LN + l] = ge;
    }
}

// ---------------- K5: out = W @ gelu(y) + bias ----------------
#define BM 64
#define BN 64
#define BKK 16
__global__ void k_gemm(const float* __restrict__ W, const float* __restrict__ bias,
                       float* __restrict__ out)
{
    int bz = blockIdx.z;                   // batch
    int bm = blockIdx.y;                   // 8
    int bn = blockIdx.x;                   // 32
    __shared__ float As[BKK][BM];
    __shared__ float Bs[BKK][BN];
    int tid = threadIdx.x;                 // 256
    int tx = tid & 15, ty = tid >> 4;      // 16x16
    float acc[4][4] = {};
    const float* Wp = W   + (bm*BM)*HN;
    const float* Gp = g_g + (size_t)(bz*HN)*LN + bn*BN;
    for (int k0 = 0; k0 < HN; k0 += BKK) {
        {   // A = W tile (64m x 16k), store transposed
            int m = tid >> 2, kq = tid & 3;
            float4 v = *(const float4*)(Wp + m*HN + k0 + kq*4);
            As[kq*4+0][m] = v.x; As[kq*4+1][m] = v.y;
            As[kq*4+2][m] = v.z; As[kq*4+3][m] = v.w;
        }
        {   // B = g tile (16k x 64n)
            int kk = tid >> 4, nq = tid & 15;
            float4 v = *(const float4*)(Gp + (size_t)(k0+kk)*LN + nq*4);
            *(float4*)&Bs[kk][nq*4] = v;
        }
        __syncthreads();
        #pragma unroll
        for (int k = 0; k < BKK; k++) {
            float av[4], bv[4];
            *(float4*)av = *(const float4*)&As[k][ty*4];
            *(float4*)bv = *(const float4*)&Bs[k][tx*4];
            #pragma unroll
            for (int i = 0; i < 4; i++)
                #pragma unroll
                for (int j = 0; j < 4; j++)
                    acc[i][j] += av[i]*bv[j];
        }
        __syncthreads();
    }
    float* Op = out + (size_t)(bz*HN + bm*BM)*LN + bn*BN;
    #pragma unroll
    for (int i = 0; i < 4; i++) {
        float bi = bias[bm*BM + ty*4 + i];
        float4 v = make_float4(acc[i][0]+bi, acc[i][1]+bi, acc[i][2]+bi, acc[i][3]+bi);
        *(float4*)(Op + (size_t)(ty*4+i)*LN + tx*4) = v;
    }
}

// ---------------- launch ----------------
extern "C" void kernel_launch(void* const* d_in, const int* in_sizes, int n_in,
                              void* d_out, int out_size)
{
    const float* u     = (const float*)d_in[0];
    const float* a     = (const float*)d_in[1];
    const float* theta = (const float*)d_in[2];
    const float* bcoef = (const float*)d_in[3];
    const float* ccoef = (const float*)d_in[4];
    const float* x0    = (const float*)d_in[5];
    const float* Dv    = (const float*)d_in[6];
    const float* W     = (const float*)d_in[7];
    const float* bias  = (const float*)d_in[8];
    float* out = (float*)d_out;

    k_tables<<<HN, 256>>>(a, theta, bcoef, ccoef, x0);
    k_chunkA<<<BSZ*HN, 256>>>(u);
    k_scan<<<BSZ*HN/8, 256>>>();
    k_main<<<BSZ*HN, 256>>>(u, Dv);
    k_gemm<<<dim3(LN/BN, HN/BM, BSZ), 256>>>(W, bias, out);
}

// round 5
// speedup vs baseline: 1.4294x; 1.4294x over previous
#include <cuda_runtime.h>
#include <math.h>

#define BSZ 8
#define HN  512
#define LN  2048
#define D2N 32
#define CN  64          // chunk length
#define NC  (LN/CN)     // 32 chunks

// ---------------- scratch (device globals; no allocation allowed) ----------------
__device__ __align__(16) float  g_f [HN*LN];          // SSM kernel f[h][l]
__device__ __align__(16) float  g_k0[HN*LN];          // init-state kernel k0[h][l]
__device__ float2               g_V [HN*CN*D2N];      // [h][m][d] = w^{C-1-m}
__device__ __align__(16) float  g_P [HN*2*D2N*CN];    // [h][dd][j]
__device__ float2               g_WC[HN*D2N];         // w^C
__device__ __align__(16) float  g_S [BSZ*HN*NC*2*D2N];// chunk states (A then in-place S)
__device__ __align__(16) float  g_g [BSZ*HN*LN];      // gelu(y)

// ---------------- K1: tables ----------------
__global__ void k_tables(const float* __restrict__ a, const float* __restrict__ th,
                         const float* __restrict__ bb, const float* __restrict__ cc,
                         const float* __restrict__ x0)
{
    int h = blockIdx.x;
    __shared__ float s_aa[D2N], s_th[D2N], s_q[D2N], s_cx[D2N];
    int tid = threadIdx.x;
    if (tid < D2N) {
        float av = a[h*D2N + tid];
        s_aa[tid] = -fabsf(av);
        s_th[tid] = th[h*D2N + tid];
        s_q [tid] = bb[h*D2N + tid] * cc[h*D2N + tid];
        s_cx[tid] = cc[h*D2N + tid] * x0[h*D2N + tid];
    }
    __syncthreads();
    const float T = 1.0f / (float)(LN - 1);

    // f and k0 grid: fast intrinsics (abs err ~1e-6, well under tolerance)
    for (int l = tid; l < LN; l += blockDim.x) {
        float z = T * (float)l;
        float accf = 0.f, acck = 0.f;
        #pragma unroll 8
        for (int d = 0; d < D2N; d++) {
            float base = __expf(s_aa[d]*z) * __cosf(s_th[d]*z);
            accf += s_q[d]  * base;
            acck += s_cx[d] * base;
        }
        g_f [h*LN + l] = 2.0f*T*accf;
        g_k0[h*LN + l] = 2.0f*acck;
    }

    // per-(h,d) power tables (precise math; these feed the recurrence)
    for (int i = tid; i < D2N*CN; i += blockDim.x) {
        int d = i & 31, m = i >> 5;
        float k = (float)(CN - 1 - m);
        float e = expf(s_aa[d]*T*k);
        g_V[(h*CN + m)*D2N + d] = make_float2(e*cosf(s_th[d]*T*k), e*sinf(s_th[d]*T*k));
    }
    for (int i = tid; i < D2N*CN; i += blockDim.x) {
        int d = i & 31, j = i >> 5;
        float k = (float)(j + 1);
        float e = expf(s_aa[d]*T*k);
        g_P[(h*2*D2N + d      )*CN + j] =  2.0f*T*s_q[d]*e*cosf(s_th[d]*T*k);
        g_P[(h*2*D2N + D2N + d)*CN + j] = -2.0f*T*s_q[d]*e*sinf(s_th[d]*T*k);
    }
    if (tid < D2N) {
        int d = tid;
        float k = (float)CN;
        float e = expf(s_aa[d]*T*k);
        g_WC[h*D2N + d] = make_float2(e*cosf(s_th[d]*T*k), e*sinf(s_th[d]*T*k));
    }
}

// ---------------- K2: per-chunk partial states A (register-blocked over chunks) ----------------
__global__ void k_chunkA(const float* __restrict__ u)
{
    int row = blockIdx.x;          // b*HN + h
    int h = row & (HN-1);
    __shared__ float  u_s[LN];
    __shared__ float2 V_s[CN*D2N];
    int tid = threadIdx.x;         // 256
    for (int i = tid; i < LN; i += 256) u_s[i] = u[row*LN + i];
    const float2* Vg = g_V + h*CN*D2N;
    for (int i = tid; i < CN*D2N; i += 256) V_s[i] = Vg[i];
    __syncthreads();

    int d  = tid & 31;
    int c0 = tid >> 5;             // 0..7; chunks c0, c0+8, c0+16, c0+24
    float ar[4] = {}, ai[4] = {};
    #pragma unroll 4
    for (int m = 0; m < CN; m++) {
        float2 v = V_s[m*D2N + d];        // 1 LDS.64 per 8 FFMA
        #pragma unroll
        for (int k = 0; k < 4; k++) {
            float um = u_s[(c0 + 8*k)*CN + m];   // warp-broadcast
            ar[k] += v.x * um;
            ai[k] += v.y * um;
        }
    }
    #pragma unroll
    for (int k = 0; k < 4; k++) {
        int idx = (row*NC + c0 + 8*k)*2*D2N;
        g_S[idx + d]       = ar[k];
        g_S[idx + D2N + d] = ai[k];
    }
}

// ---------------- K3: cross-chunk state scan (in place) ----------------
__global__ void k_scan()
{
    int row = blockIdx.x*8 + (threadIdx.x >> 5);
    int d   = threadIdx.x & 31;
    float2 wc = g_WC[(row & (HN-1))*D2N + d];
    float sr = 0.f, si = 0.f;
    for (int c = 0; c < NC; c++) {
        int idx = (row*NC + c)*2*D2N;
        float ar = g_S[idx + d];
        float ai = g_S[idx + D2N + d];
        g_S[idx + d]       = sr;   // state entering chunk c
        g_S[idx + D2N + d] = si;
        float nsr = wc.x*sr - wc.y*si + ar;
        si        = wc.x*si + wc.y*sr + ai;
        sr = nsr;
    }
}

// ---------------- K4: intra-chunk conv + cross term + epilogue + GELU ----------------
// Thread tile: 2 chunks x 4 consecutive l. Sliding f-window, padded transposed u/S.
__global__ void __launch_bounds__(256) k_main(const float* __restrict__ u,
                                              const float* __restrict__ Din)
{
    int row = blockIdx.x;
    int h = row & (HN-1);
    __shared__ float ut[CN*33];                 // u transposed [m][c], pad 33
    __shared__ __align__(16) float fbuf[4+CN];  // 4-zero guard + f[0..63]
    __shared__ __align__(16) float P_s[2*D2N*CN];   // [dd][jj]; later reused for e_t
    __shared__ float S_s[NC*65];                // [c][dd] pad 65; later reused for out staging
    int tid = threadIdx.x;                      // 256

    for (int i = tid; i < LN; i += 256) {
        float v = u[row*LN + i];
        ut[(i & 63)*33 + (i >> 6)] = v;         // conflict-free (bank stride 1)
    }
    const float4* Pg = (const float4*)(g_P + h*2*D2N*CN);
    for (int i = tid; i < (2*D2N*CN)/4; i += 256) ((float4*)P_s)[i] = Pg[i];
    if (tid < 4)  fbuf[tid] = 0.f;
    if (tid < CN) fbuf[4+tid] = g_f[h*LN + tid];
    for (int i = tid; i < NC*2*D2N; i += 256)
        S_s[(i >> 6)*65 + (i & 63)] = g_S[row*NC*2*D2N + i];
    __syncthreads();

    int cp  = tid & 15;            // chunk pair id -> chunks cp, cp+16
    int jjg = tid >> 4;            // warp-contiguous jj groups (triangle early-exit)
    int jj4 = jjg * 4;
    int c0 = cp, c1 = cp + 16;
    float u0f   = ut[0];
    float coefU = Din[h] - 0.5f * fbuf[4];

    float y0[4] = {0.f,0.f,0.f,0.f}, y1[4] = {0.f,0.f,0.f,0.f};

    // intra-chunk triangular conv with sliding window of f
    float4 w = *(const float4*)&fbuf[4 + jj4];
    float w0 = w.x, w1 = w.y, w2 = w.z, w3 = w.w;
    int mmax = jj4 + 3;
    #pragma unroll 4
    for (int m = 0; m <= mmax; m++) {
        float ua = ut[m*33 + c0];
        float ub = ut[m*33 + c1];
        y0[0] += ua*w0; y0[1] += ua*w1; y0[2] += ua*w2; y0[3] += ua*w3;
        y1[0] += ub*w0; y1[1] += ub*w1; y1[2] += ub*w2; y1[3] += ub*w3;
        w3 = w2; w2 = w1; w1 = w0;
        w0 = fbuf[3 + jj4 - m];                 // guard zeros cover m>=jj4+r
    }

    // cross-chunk term: y += P[dd][jj] * S[c][dd]
    #pragma unroll 4
    for (int dd = 0; dd < 2*D2N; dd++) {
        float4 p = *(const float4*)&P_s[dd*CN + jj4];  // broadcast over cp lanes
        float sa = S_s[c0*65 + dd];
        float sb = S_s[c1*65 + dd];
        y0[0] += p.x*sa; y0[1] += p.y*sa; y0[2] += p.z*sa; y0[3] += p.w*sa;
        y1[0] += p.x*sb; y1[1] += p.y*sb; y1[2] += p.z*sb; y1[3] += p.w*sb;
    }

    // stage combined epilogue term e[l] = k0[l] - 0.5*u0*f[l], transposed (reuse P_s)
    __syncthreads();
    for (int i = tid; i < LN; i += 256) {
        float e = g_k0[h*LN + i] - 0.5f*u0f*g_f[h*LN + i];
        P_s[(i & 63)*33 + (i >> 6)] = e;        // 2112 floats <= 4096 capacity
    }
    __syncthreads();

    // epilogue + GELU -> staged into S_s (padded [c][jj]) for coalesced writeout
    #pragma unroll
    for (int r = 0; r < 4; r++) {
        int jr = jj4 + r;
        float uv0 = ut[jr*33 + c0];
        float uv1 = ut[jr*33 + c1];
        float ya = y0[r] + P_s[jr*33 + c0] + coefU*uv0;
        float yb = y1[r] + P_s[jr*33 + c1] + coefU*uv1;
        float ga = 0.5f * ya * (1.0f + erff(ya * 0.70710678118654752f));
        float gb = 0.5f * yb * (1.0f + erff(yb * 0.70710678118654752f));
        S_s[c0*65 + jr] = ga;
        S_s[c1*65 + jr] = gb;
    }
    __syncthreads();
    for (int i = tid; i < LN; i += 256)
        g_g[row*LN + i] = S_s[(i >> 6)*65 + (i & 63)];
}

// ---------------- K5: out = W @ gelu(y) + bias ----------------
#define BM 64
#define BN 64
#define BKK 16
__global__ void k_gemm(const float* __restrict__ W, const float* __restrict__ bias,
                       float* __restrict__ out)
{
    int bz = blockIdx.z;                   // batch
    int bm = blockIdx.y;                   // 8
    int bn = blockIdx.x;                   // 32
    __shared__ float As[BKK][BM];
    __shared__ float Bs[BKK][BN];
    int tid = threadIdx.x;                 // 256
    int tx = tid & 15, ty = tid >> 4;      // 16x16
    float acc[4][4] = {};
    const float* Wp = W   + (bm*BM)*HN;
    const float* Gp = g_g + (size_t)(bz*HN)*LN + bn*BN;
    for (int k0 = 0; k0 < HN; k0 += BKK) {
        {   // A = W tile (64m x 16k), store transposed
            int m = tid >> 2, kq = tid & 3;
            float4 v = *(const float4*)(Wp + m*HN + k0 + kq*4);
            As[kq*4+0][m] = v.x; As[kq*4+1][m] = v.y;
            As[kq*4+2][m] = v.z; As[kq*4+3][m] = v.w;
        }
        {   // B = g tile (16k x 64n)
            int kk = tid >> 4, nq = tid & 15;
            float4 v = *(const float4*)(Gp + (size_t)(k0+kk)*LN + nq*4);
            *(float4*)&Bs[kk][nq*4] = v;
        }
        __syncthreads();
        #pragma unroll
        for (int k = 0; k < BKK; k++) {
            float av[4], bv[4];
            *(float4*)av = *(const float4*)&As[k][ty*4];
            *(float4*)bv = *(const float4*)&Bs[k][tx*4];
            #pragma unroll
            for (int i = 0; i < 4; i++)
                #pragma unroll
                for (int j = 0; j < 4; j++)
                    acc[i][j] += av[i]*bv[j];
        }
        __syncthreads();
    }
    float* Op = out + (size_t)(bz*HN + bm*BM)*LN + bn*BN;
    #pragma unroll
    for (int i = 0; i < 4; i++) {
        float bi = bias[bm*BM + ty*4 + i];
        float4 v = make_float4(acc[i][0]+bi, acc[i][1]+bi, acc[i][2]+bi, acc[i][3]+bi);
        *(float4*)(Op + (size_t)(ty*4+i)*LN + tx*4) = v;
    }
}

// ---------------- launch ----------------
extern "C" void kernel_launch(void* const* d_in, const int* in_sizes, int n_in,
                              void* d_out, int out_size)
{
    const float* u     = (const float*)d_in[0];
    const float* a     = (const float*)d_in[1];
    const float* theta = (const float*)d_in[2];
    const float* bcoef = (const float*)d_in[3];
    const float* ccoef = (const float*)d_in[4];
    const float* x0    = (const float*)d_in[5];
    const float* Dv    = (const float*)d_in[6];
    const float* W     = (const float*)d_in[7];
    const float* bias  = (const float*)d_in[8];
    float* out = (float*)d_out;

    k_tables<<<HN, 256>>>(a, theta, bcoef, ccoef, x0);
    k_chunkA<<<BSZ*HN, 256>>>(u);
    k_scan<<<BSZ*HN/8, 256>>>();
    k_main<<<BSZ*HN, 256>>>(u, Dv);
    k_gemm<<<dim3(LN/BN, HN/BM, BSZ), 256>>>(W, bias, out);
}

// round 8
// speedup vs baseline: 2.1147x; 1.4794x over previous
#include <cuda_runtime.h>
#include <cuda_bf16.h>
#include <cstdint>
#include <math.h>

#define BSZ 8
#define HN  512
#define LN  2048
#define D2N 32
#define CN  64          // chunk length
#define NC  (LN/CN)     // 32 chunks

// ---------------- scratch (device globals; no allocation allowed) ----------------
__device__ __align__(16) float  g_f [HN*LN];
__device__ __align__(16) float  g_k0[HN*LN];
__device__ float2               g_V [HN*CN*D2N];      // [h][m][d] = w^{C-1-m}
__device__ __align__(16) float  g_P [HN*2*D2N*CN];    // [h][dd][j]
__device__ float2               g_WC[HN*D2N];         // w^C
__device__ __align__(16) float  g_S [BSZ*HN*NC*2*D2N];
__device__ __align__(16) __nv_bfloat16 g_Wh[HN*HN], g_Wl[HN*HN];
__device__ __align__(16) __nv_bfloat16 g_gh[BSZ*HN*LN], g_gl[BSZ*HN*LN];

// ---------------- K1: f/k0 grid via phasor rotation ----------------
__global__ void __launch_bounds__(128) k_tables(const float* __restrict__ a,
                                                const float* __restrict__ th,
                                                const float* __restrict__ bb,
                                                const float* __restrict__ cc,
                                                const float* __restrict__ x0)
{
    int h = blockIdx.x;
    __shared__ float4 tab[D2N];          // (wr128, wi128, q, cx)
    __shared__ float s_aa[D2N], s_th[D2N];
    int tid = threadIdx.x;
    const float T = 1.0f / (float)(LN - 1);
    if (tid < D2N) {
        float aa = -fabsf(a[h*D2N + tid]);
        float t0 = th[h*D2N + tid];
        float q  = bb[h*D2N + tid] * cc[h*D2N + tid];
        float cx = cc[h*D2N + tid] * x0[h*D2N + tid];
        s_aa[tid] = aa; s_th[tid] = t0;
        float zs = 128.0f * T;
        float e = __expf(aa*zs);
        float si, co; __sincosf(t0*zs, &si, &co);
        tab[tid] = make_float4(e*co, e*si, q, cx);
    }
    __syncthreads();

    // thread handles l = tid + 128*s, s = 0..15; init at z = T*tid (small args)
    float z = T * (float)tid;
    float vr[D2N], vi[D2N];
    #pragma unroll
    for (int d = 0; d < D2N; d++) {
        float e = __expf(s_aa[d]*z);
        float si, co; __sincosf(s_th[d]*z, &si, &co);
        vr[d] = e*co; vi[d] = e*si;
    }
    for (int s = 0; s < 16; s++) {
        float fa = 0.f, ka = 0.f;
        #pragma unroll
        for (int d = 0; d < D2N; d++) {
            float4 t = tab[d];
            fa += t.z * vr[d];
            ka += t.w * vr[d];
            float nr = vr[d]*t.x - vi[d]*t.y;
            vi[d]    = vr[d]*t.y + vi[d]*t.x;
            vr[d] = nr;
        }
        g_f [h*LN + tid + 128*s] = 2.0f*T*fa;
        g_k0[h*LN + tid + 128*s] = 2.0f*ka;
    }
}

// ---------------- K1b: V/P/WC tables, fully elementwise ----------------
__global__ void k_tables2(const float* __restrict__ a, const float* __restrict__ th,
                          const float* __restrict__ bb, const float* __restrict__ cc)
{
    int t = blockIdx.x*256 + threadIdx.x;        // 2 * 2^20 threads
    int which = t >> 20;
    int r = t & 0xFFFFF;
    const float T = 1.0f / (float)(LN - 1);
    if (which == 0) {
        int d = r & 31, m = (r >> 5) & 63, h = r >> 11;
        float aa = -fabsf(a[h*D2N + d]);
        float t0 = th[h*D2N + d];
        float k = (float)(CN - 1 - m);
        float e = __expf(aa*T*k);
        float si, co; __sincosf(t0*T*k, &si, &co);
        g_V[(h*CN + m)*D2N + d] = make_float2(e*co, e*si);
        if (m == 0) {
            float kc = (float)CN;
            float ec = __expf(aa*T*kc);
            float s2, c2; __sincosf(t0*T*kc, &s2, &c2);
            g_WC[h*D2N + d] = make_float2(ec*c2, ec*s2);
        }
    } else {
        int j = r & 63, d = (r >> 6) & 31, h = r >> 11;
        float aa = -fabsf(a[h*D2N + d]);
        float t0 = th[h*D2N + d];
        float q  = bb[h*D2N + d] * cc[h*D2N + d];
        float k = (float)(j + 1);
        float e = __expf(aa*T*k);
        float si, co; __sincosf(t0*T*k, &si, &co);
        g_P[(h*2*D2N + d      )*CN + j] =  2.0f*T*q*e*co;
        g_P[(h*2*D2N + D2N + d)*CN + j] = -2.0f*T*q*e*si;
    }
}

// ---------------- K1c: split W into bf16 hi/lo ----------------
__global__ void k_splitW(const float* __restrict__ W)
{
    int i = blockIdx.x*256 + threadIdx.x;
    float w = W[i];
    __nv_bfloat16 hi = __float2bfloat16(w);
    g_Wh[i] = hi;
    g_Wl[i] = __float2bfloat16(w - __bfloat162float(hi));
}

// ---------------- K2: per-chunk partial states A ----------------
__global__ void k_chunkA(const float* __restrict__ u)
{
    int row = blockIdx.x;
    int h = row & (HN-1);
    __shared__ float  u_s[LN];
    __shared__ float2 V_s[CN*D2N];
    int tid = threadIdx.x;         // 256
    for (int i = tid; i < LN; i += 256) u_s[i] = u[row*LN + i];
    const float2* Vg = g_V + h*CN*D2N;
    for (int i = tid; i < CN*D2N; i += 256) V_s[i] = Vg[i];
    __syncthreads();

    int d  = tid & 31;
    int c0 = tid >> 5;
    float ar[4] = {}, ai[4] = {};
    #pragma unroll 4
    for (int m = 0; m < CN; m++) {
        float2 v = V_s[m*D2N + d];
        #pragma unroll
        for (int k = 0; k < 4; k++) {
            float um = u_s[(c0 + 8*k)*CN + m];
            ar[k] += v.x * um;
            ai[k] += v.y * um;
        }
    }
    #pragma unroll
    for (int k = 0; k < 4; k++) {
        int idx = (row*NC + c0 + 8*k)*2*D2N;
        g_S[idx + d]       = ar[k];
        g_S[idx + D2N + d] = ai[k];
    }
}

// ---------------- K3: cross-chunk state scan ----------------
__global__ void k_scan()
{
    int row = blockIdx.x*8 + (threadIdx.x >> 5);
    int d   = threadIdx.x & 31;
    float2 wc = g_WC[(row & (HN-1))*D2N + d];
    float sr = 0.f, si = 0.f;
    for (int c = 0; c < NC; c++) {
        int idx = (row*NC + c)*2*D2N;
        float ar = g_S[idx + d];
        float ai = g_S[idx + D2N + d];
        g_S[idx + d]       = sr;
        g_S[idx + D2N + d] = si;
        float nsr = wc.x*sr - wc.y*si + ar;
        si        = wc.x*si + wc.y*sr + ai;
        sr = nsr;
    }
}

// ---------------- K4: intra-chunk conv + cross term + GELU + bf16 split ----------------
__global__ void __launch_bounds__(256) k_main(const float* __restrict__ u,
                                              const float* __restrict__ Din)
{
    int row = blockIdx.x;
    int h = row & (HN-1);
    __shared__ float ut[CN*33];
    __shared__ __align__(16) float fbuf[4+CN];
    __shared__ __align__(16) float P_s[2*D2N*CN];
    __shared__ float S_s[NC*65];
    int tid = threadIdx.x;

    for (int i = tid; i < LN; i += 256) {
        float v = u[row*LN + i];
        ut[(i & 63)*33 + (i >> 6)] = v;
    }
    const float4* Pg = (const float4*)(g_P + h*2*D2N*CN);
    for (int i = tid; i < (2*D2N*CN)/4; i += 256) ((float4*)P_s)[i] = Pg[i];
    if (tid < 4)  fbuf[tid] = 0.f;
    if (tid < CN) fbuf[4+tid] = g_f[h*LN + tid];
    for (int i = tid; i < NC*2*D2N; i += 256)
        S_s[(i >> 6)*65 + (i & 63)] = g_S[row*NC*2*D2N + i];
    __syncthreads();

    int cp  = tid & 15;
    int jjg = tid >> 4;
    int jj4 = jjg * 4;
    int c0 = cp, c1 = cp + 16;
    float u0f   = ut[0];
    float coefU = Din[h] - 0.5f * fbuf[4];

    float y0[4] = {0.f,0.f,0.f,0.f}, y1[4] = {0.f,0.f,0.f,0.f};

    float4 w = *(const float4*)&fbuf[4 + jj4];
    float w0 = w.x, w1 = w.y, w2 = w.z, w3 = w.w;
    int mmax = jj4 + 3;
    #pragma unroll 4
    for (int m = 0; m <= mmax; m++) {
        float ua = ut[m*33 + c0];
        float ub = ut[m*33 + c1];
        y0[0] += ua*w0; y0[1] += ua*w1; y0[2] += ua*w2; y0[3] += ua*w3;
        y1[0] += ub*w0; y1[1] += ub*w1; y1[2] += ub*w2; y1[3] += ub*w3;
        w3 = w2; w2 = w1; w1 = w0;
        w0 = fbuf[3 + jj4 - m];
    }

    #pragma unroll 4
    for (int dd = 0; dd < 2*D2N; dd++) {
        float4 p = *(const float4*)&P_s[dd*CN + jj4];
        float sa = S_s[c0*65 + dd];
        float sb = S_s[c1*65 + dd];
        y0[0] += p.x*sa; y0[1] += p.y*sa; y0[2] += p.z*sa; y0[3] += p.w*sa;
        y1[0] += p.x*sb; y1[1] += p.y*sb; y1[2] += p.z*sb; y1[3] += p.w*sb;
    }

    __syncthreads();
    for (int i = tid; i < LN; i += 256) {
        float e = g_k0[h*LN + i] - 0.5f*u0f*g_f[h*LN + i];
        P_s[(i & 63)*33 + (i >> 6)] = e;
    }
    __syncthreads();

    #pragma unroll
    for (int r = 0; r < 4; r++) {
        int jr = jj4 + r;
        float uv0 = ut[jr*33 + c0];
        float uv1 = ut[jr*33 + c1];
        float ya = y0[r] + P_s[jr*33 + c0] + coefU*uv0;
        float yb = y1[r] + P_s[jr*33 + c1] + coefU*uv1;
        float ga = 0.5f * ya * (1.0f + erff(ya * 0.70710678118654752f));
        float gb = 0.5f * yb * (1.0f + erff(yb * 0.70710678118654752f));
        S_s[c0*65 + jr] = ga;
        S_s[c1*65 + jr] = gb;
    }
    __syncthreads();
    for (int i = tid; i < LN; i += 256) {
        float v = S_s[(i >> 6)*65 + (i & 63)];
        __nv_bfloat16 hi = __float2bfloat16(v);
        g_gh[row*LN + i] = hi;
        g_gl[row*LN + i] = __float2bfloat16(v - __bfloat162float(hi));
    }
}

// ---------------- K5: tensor-core GEMM, 3-product bf16 split ----------------
#define ASTR 40    // bf16 elems per A smem row (80B, odd multiple of 16B)
#define BSTR 136   // bf16 elems per B smem row (272B, odd multiple of 16B)

__device__ __forceinline__ void ldsm_x4(uint32_t &r0, uint32_t &r1, uint32_t &r2, uint32_t &r3,
                                        uint32_t addr) {
    asm volatile("ldmatrix.sync.aligned.m8n8.x4.shared.b16 {%0,%1,%2,%3}, [%4];"
                 : "=r"(r0), "=r"(r1), "=r"(r2), "=r"(r3) : "r"(addr));
}
__device__ __forceinline__ void ldsm_x2t(uint32_t &r0, uint32_t &r1, uint32_t addr) {
    asm volatile("ldmatrix.sync.aligned.m8n8.x2.trans.shared.b16 {%0,%1}, [%2];"
                 : "=r"(r0), "=r"(r1) : "r"(addr));
}
__device__ __forceinline__ void mma_bf16(float* c, const uint32_t* a, const uint32_t* b) {
    asm volatile("mma.sync.aligned.m16n8k16.row.col.f32.bf16.bf16.f32 "
                 "{%0,%1,%2,%3},{%4,%5,%6,%7},{%8,%9},{%0,%1,%2,%3};"
                 : "+f"(c[0]), "+f"(c[1]), "+f"(c[2]), "+f"(c[3])
                 : "r"(a[0]), "r"(a[1]), "r"(a[2]), "r"(a[3]), "r"(b[0]), "r"(b[1]));
}

__global__ void __launch_bounds__(256) k_gemm_tc(const float* __restrict__ bias,
                                                 float* __restrict__ out)
{
    int bz = blockIdx.z, bm = blockIdx.y, bn = blockIdx.x;
    __shared__ __nv_bfloat16 sAh[128*ASTR], sAl[128*ASTR];
    __shared__ __nv_bfloat16 sBh[32*BSTR],  sBl[32*BSTR];
    int tid  = threadIdx.x;
    int warp = tid >> 5, lane = tid & 31;
    int wm = (warp >> 2) * 64;       // warp m offset within block tile
    int wn = (warp & 3) * 32;        // warp n offset

    uint32_t sAh_u = (uint32_t)__cvta_generic_to_shared(sAh);
    uint32_t sAl_u = (uint32_t)__cvta_generic_to_shared(sAl);
    uint32_t sBh_u = (uint32_t)__cvta_generic_to_shared(sBh);
    uint32_t sBl_u = (uint32_t)__cvta_generic_to_shared(sBl);

    float acc[4][4][4];
    #pragma unroll
    for (int i = 0; i < 4; i++)
        #pragma unroll
        for (int j = 0; j < 4; j++)
            #pragma unroll
            for (int q = 0; q < 4; q++) acc[i][j][q] = 0.f;

    const __nv_bfloat16* Gh = g_gh + (size_t)bz*HN*LN;
    const __nv_bfloat16* Gl = g_gl + (size_t)bz*HN*LN;

    for (int k0 = 0; k0 < HN; k0 += 32) {
        // load A tiles (128m x 32k) and B tiles (32k x 128n)
        #pragma unroll
        for (int rpt = 0; rpt < 2; rpt++) {
            int idx = tid + rpt*256;
            int arow = idx >> 2, acol = (idx & 3) * 8;
            const __nv_bfloat16* src = g_Wh + (size_t)(bm*128 + arow)*HN + k0 + acol;
            *(uint4*)&sAh[arow*ASTR + acol] = *(const uint4*)src;
            src = g_Wl + (size_t)(bm*128 + arow)*HN + k0 + acol;
            *(uint4*)&sAl[arow*ASTR + acol] = *(const uint4*)src;

            int brow = idx >> 4, bcol = (idx & 15) * 8;
            const __nv_bfloat16* bsrc = Gh + (size_t)(k0 + brow)*LN + bn*128 + bcol;
            *(uint4*)&sBh[brow*BSTR + bcol] = *(const uint4*)bsrc;
            bsrc = Gl + (size_t)(k0 + brow)*LN + bn*128 + bcol;
            *(uint4*)&sBl[brow*BSTR + bcol] = *(const uint4*)bsrc;
        }
        __syncthreads();

        #pragma unroll
        for (int kk = 0; kk < 32; kk += 16) {
            uint32_t ah[4][4], al[4][4], bh[4][2], bl[4][2];
            int arow = wm + (lane & 7) + ((lane >> 3) & 1) * 8;
            int acol = kk + (lane >> 4) * 8;
            #pragma unroll
            for (int mi = 0; mi < 4; mi++) {
                uint32_t ad = sAh_u + (uint32_t)(((arow + mi*16)*ASTR + acol) * 2);
                ldsm_x4(ah[mi][0], ah[mi][1], ah[mi][2], ah[mi][3], ad);
                ad = sAl_u + (uint32_t)(((arow + mi*16)*ASTR + acol) * 2);
                ldsm_x4(al[mi][0], al[mi][1], al[mi][2], al[mi][3], ad);
            }
            int brow = kk + (lane & 15);
            #pragma unroll
            for (int ni = 0; ni < 4; ni++) {
                uint32_t bd = sBh_u + (uint32_t)((brow*BSTR + wn + ni*8) * 2);
                ldsm_x2t(bh[ni][0], bh[ni][1], bd);
                bd = sBl_u + (uint32_t)((brow*BSTR + wn + ni*8) * 2);
                ldsm_x2t(bl[ni][0], bl[ni][1], bd);
            }
            #pragma unroll
            for (int mi = 0; mi < 4; mi++)
                #pragma unroll
                for (int ni = 0; ni < 4; ni++) {
                    mma_bf16(acc[mi][ni], ah[mi], bh[ni]);
                    mma_bf16(acc[mi][ni], ah[mi], bl[ni]);
                    mma_bf16(acc[mi][ni], al[mi], bh[ni]);
                }
        }
        __syncthreads();
    }

    // epilogue
    #pragma unroll
    for (int mi = 0; mi < 4; mi++) {
        int m = bm*128 + wm + mi*16 + (lane >> 2);
        float bi0 = bias[m], bi8 = bias[m + 8];
        #pragma unroll
        for (int ni = 0; ni < 4; ni++) {
            int n = bn*128 + wn + ni*8 + (lane & 3)*2;
            float2 v0 = make_float2(acc[mi][ni][0] + bi0, acc[mi][ni][1] + bi0);
            float2 v1 = make_float2(acc[mi][ni][2] + bi8, acc[mi][ni][3] + bi8);
            *(float2*)(out + (size_t)(bz*HN + m)*LN + n)     = v0;
            *(float2*)(out + (size_t)(bz*HN + m + 8)*LN + n) = v1;
        }
    }
}

// ---------------- launch ----------------
extern "C" void kernel_launch(void* const* d_in, const int* in_sizes, int n_in,
                              void* d_out, int out_size)
{
    const float* u     = (const float*)d_in[0];
    const float* a     = (const float*)d_in[1];
    const float* theta = (const float*)d_in[2];
    const float* bcoef = (const float*)d_in[3];
    const float* ccoef = (const float*)d_in[4];
    const float* x0    = (const float*)d_in[5];
    const float* Dv    = (const float*)d_in[6];
    const float* W     = (const float*)d_in[7];
    const float* bias  = (const float*)d_in[8];
    float* out = (float*)d_out;

    k_tables <<<HN, 128>>>(a, theta, bcoef, ccoef, x0);
    k_tables2<<<8192, 256>>>(a, theta, bcoef, ccoef);
    k_splitW <<<HN*HN/256, 256>>>(W);
    k_chunkA <<<BSZ*HN, 256>>>(u);
    k_scan   <<<BSZ*HN/8, 256>>>();
    k_main   <<<BSZ*HN, 256>>>(u, Dv);
    k_gemm_tc<<<dim3(LN/128, HN/128, BSZ), 256>>>(bias, out);
}